// round 5
// baseline (speedup 1.0000x reference)
#include <cuda_runtime.h>
#include <cstdint>

// ============================================================================
// Binary conv1d (sign x sign) + maxpool(7,2) + per-channel threshold.
// IMMA mma.sync.m16n8k64.s4 (±1 encoded as s4 0x1/0xF): K=448 in 7 steps,
// each step = one conv tap. Cross-tile prefetch pipelining + 2 CTAs/SM.
// ============================================================================

#define BATCH 64
#define CIN 64
#define LEN 16384
#define COUT 128
#define LOUT 8189
#define TILE_OUT 29
#define TILES_PER_B 283
#define TOTAL_TILES (BATCH * TILES_PER_B)   // 18112
#define NTHREADS 256
#define GRID 296                             // 2 CTAs per SM

#define KSTEPS 7               // K = 448 = 7 * 64 (one tap per step)
#define X_PITCH 48             // bytes per sign row (32 B data + 16 pad)
#define CV_PITCH 129

#define MMA_S4(d, a, b0_, b1_)                                                 \
    asm volatile(                                                              \
        "mma.sync.aligned.m16n8k64.row.col.s32.s4.s4.s32 "                     \
        "{%0,%1,%2,%3},{%4,%5,%6,%7},{%8,%9},{%0,%1,%2,%3};"                   \
        : "+r"((d)[0]), "+r"((d)[1]), "+r"((d)[2]), "+r"((d)[3])               \
        : "r"((a)[0]), "r"((a)[1]), "r"((a)[2]), "r"((a)[3]),                  \
          "r"(b0_), "r"(b1_))

__global__ void __launch_bounds__(NTHREADS, 2)
binconv_kernel(const float* __restrict__ I, const float* __restrict__ W,
               const float* __restrict__ TP, const float* __restrict__ TMi,
               const float* __restrict__ PS, const float* __restrict__ MS,
               float* __restrict__ out)
{
    __shared__ int CV[64 * CV_PITCH];              // 33.0 KB
    __shared__ unsigned char X[70 * X_PITCH];      // 3.3 KB nibble sign tile

    const int tid  = threadIdx.x;
    const int lane = tid & 31;
    const int wid  = tid >> 5;       // 0..7 -> m16 tile (8 * 16 = M 128)
    const int gr   = lane >> 2;      // 0..7
    const int tg   = lane & 3;       // 0..3

    const int co   = tid & 127;
    const int half = tid >> 7;
    const float rtp = TP[co], rtm = TMi[co], rps = PS[co], rms = MS[co];

    // ---- stationary A fragments (weight signs as s4): 28 regs/thread ----
    // m16n8k64 A frag (row-major 16x64 s4): reg j covers
    //   row = wid*16 + gr + (j&1)*8, k-nibbles = (j>>1)*32 + tg*8 + i
    // kappa = tap*64 + ci -> step s handles tap s; ci = (j>>1)*32 + tg*8 + i
    uint32_t A[KSTEPS][4];
    #pragma unroll
    for (int s = 0; s < KSTEPS; s++) {
        #pragma unroll
        for (int j = 0; j < 4; j++) {
            const int row = wid * 16 + gr + (j & 1) * 8;
            const int ci0 = (j >> 1) * 32 + tg * 8;
            uint32_t r = 0;
            #pragma unroll
            for (int i = 0; i < 8; i++) {
                const float w = W[row * 448 + (ci0 + i) * 7 + s];
                r |= ((w < 0.f) ? 0xFu : 0x1u) << (4 * i);
            }
            A[s][j] = r;
        }
    }

    // ---- cross-tile prefetch registers: 5 items x 4 floats ----
    float pf[5][4];

    auto prefetch = [&](unsigned g) {
        if (g >= TOTAL_TILES) return;
        const int b  = (int)(g / TILES_PER_B);
        const int P0 = ((int)g - b * TILES_PER_B) * TILE_OUT * 2;
        const float* Ib = I + (size_t)b * (size_t)CIN * LEN;
        #pragma unroll
        for (int it = 0; it < 5; it++) {
            const int idx = tid + it * NTHREADS;
            if (idx < 16 * 70) {
                const int ci4 = idx / 70;
                const int p   = idx - ci4 * 70;
                const int gl  = P0 - 3 + p;
                const bool inb = (gl >= 0) && (gl < LEN);
                const float* ip = Ib + (size_t)(ci4 * 4) * LEN + gl;
                pf[it][0] = inb ? ip[0]       : -1.f;
                pf[it][1] = inb ? ip[LEN]     : -1.f;
                pf[it][2] = inb ? ip[2 * LEN] : -1.f;
                pf[it][3] = inb ? ip[3 * LEN] : -1.f;
            }
        }
    };

    unsigned g = (unsigned)blockIdx.x;
    prefetch(g);

    while (g < TOTAL_TILES) {
        const unsigned gn = g + GRID;
        const int b  = (int)(g / TILES_PER_B);
        const int jt = (int)g - b * TILES_PER_B;
        const int t0 = jt * TILE_OUT;
        const int nt = min(TILE_OUT, LOUT - t0);

        // ---- convert prefetched floats -> nibble sign tile X[p][ci/2] ----
        // nibble i of byte q = sign of channel 2q + i (+1 -> 0x1, -1 -> 0xF)
        #pragma unroll
        for (int it = 0; it < 5; it++) {
            const int idx = tid + it * NTHREADS;
            if (idx < 16 * 70) {
                const int ci4 = idx / 70;
                const int p   = idx - ci4 * 70;
                const uint16_t pk =
                      (uint16_t)((pf[it][0] < 0.f) ? 0xFu : 0x1u)
                    | (uint16_t)(((pf[it][1] < 0.f) ? 0xFu : 0x1u) << 4)
                    | (uint16_t)(((pf[it][2] < 0.f) ? 0xFu : 0x1u) << 8)
                    | (uint16_t)(((pf[it][3] < 0.f) ? 0xFu : 0x1u) << 12);
                *(uint16_t*)&X[p * X_PITCH + ci4 * 2] = pk;
            }
        }
        __syncthreads();            // X ready; prev tile's CV pool reads done

        // ---- kick off next tile's global loads (hidden under MMA) ----
        prefetch(gn);

        // ---- MMA mainloop: 56 IMMA.s4 + 112 LDS.32 per warp ----
        int acc[8][4];
        #pragma unroll
        for (int n8 = 0; n8 < 8; n8++)
            #pragma unroll
            for (int r = 0; r < 4; r++) acc[n8][r] = 0;

        #pragma unroll
        for (int s = 0; s < KSTEPS; s++) {
            #pragma unroll
            for (int n8 = 0; n8 < 8; n8++) {
                const int prel = n8 * 8 + gr + s;      // conv pos row for tap s
                const uint32_t* bp = (const uint32_t*)&X[prel * X_PITCH];
                const uint32_t b0 = bp[tg];            // ci = tg*8 .. +7
                const uint32_t b1 = bp[4 + tg];        // ci = 32+tg*8 .. +7
                MMA_S4(acc[n8], A[s], b0, b1);
            }
        }

        // ---- stage conv results to CV[n][co] ----
        #pragma unroll
        for (int n8 = 0; n8 < 8; n8++) {
            const int n0 = n8 * 8 + tg * 2;
            const int r0 = wid * 16 + gr;
            CV[n0 * CV_PITCH + r0]           = acc[n8][0];
            CV[(n0 + 1) * CV_PITCH + r0]     = acc[n8][1];
            CV[n0 * CV_PITCH + r0 + 8]       = acc[n8][2];
            CV[(n0 + 1) * CV_PITCH + r0 + 8] = acc[n8][3];
        }
        __syncthreads();            // CV ready; all MMA reads of X done

        // ---- pool(7,2) + threshold + store ----
        {
            const int jo0 = half * 15;
            if (jo0 < nt) {
                float* ob = out + ((size_t)b * COUT + co) * LOUT + t0;
                int qa = max(CV[(2 * jo0) * CV_PITCH + co],
                             CV[(2 * jo0 + 1) * CV_PITCH + co]);
                int qb = max(CV[(2 * jo0 + 2) * CV_PITCH + co],
                             CV[(2 * jo0 + 3) * CV_PITCH + co]);
                #pragma unroll
                for (int k = 0; k < 15; k++) {
                    const int jo = jo0 + k;
                    if (jo < nt && jo < 29) {
                        const int l0 = CV[(2 * jo + 4) * CV_PITCH + co];
                        const int l1 = CV[(2 * jo + 5) * CV_PITCH + co];
                        const int l2 = CV[(2 * jo + 6) * CV_PITCH + co];
                        const int qc = max(l0, l1);
                        const int mi = max(max(qa, qb), max(qc, l2));
                        const float mx = (float)mi;
                        const float pos = (mx > rtp) ? rps : -rps;
                        const float neg = (mx > rtm) ? rms : -rms;
                        ob[jo] = (mx >= 0.f) ? pos : neg;
                        qa = qb; qb = qc;
                    }
                }
            }
        }

        g = gn;
    }
}

extern "C" void kernel_launch(void* const* d_in, const int* in_sizes, int n_in,
                              void* d_out, int out_size) {
    const float* I  = (const float*)d_in[0];
    const float* W  = (const float*)d_in[1];
    const float* tp = (const float*)d_in[2];
    const float* tm = (const float*)d_in[3];
    const float* ps = (const float*)d_in[4];
    const float* ms = (const float*)d_in[5];
    float* out = (float*)d_out;

    binconv_kernel<<<GRID, NTHREADS>>>(I, W, tp, tm, ps, ms, out);
}

// round 6
// speedup vs baseline: 2.2110x; 2.2110x over previous
#include <cuda_runtime.h>
#include <cstdint>

// ============================================================================
// Binary conv1d (sign x sign) + maxpool(7,2) + per-channel threshold.
// IMMA mma.sync.m16n8k32.s8 (native on sm_103; s4 is ALU-emulated -> reverted).
// Cross-tile register prefetch, 2 CTAs/SM, and a wavefront-cheap epilogue:
// pool results staged in smem OUT[co][jo], then stored coalesced (lane = jo).
// ============================================================================

#define BATCH 64
#define CIN 64
#define LEN 16384
#define COUT 128
#define LOUT 8189
#define TILE_OUT 29
#define TILES_PER_B 283
#define TOTAL_TILES (BATCH * TILES_PER_B)   // 18112
#define NTHREADS 256
#define GRID 296                             // 2 CTAs per SM

#define KSTEPS 14              // K = 448 = 14 * 32
#define X_PITCH 80             // 64 B + 16 pad: conflict-free LDS.32 frag loads
#define CV_PITCH 129

// dynamic smem layout (bytes)
#define SM_CV   0                            // int  CV[64*129]  = 33024 B
#define SM_OUT  (64 * CV_PITCH * 4)          // float OUT[128*29] = 14848 B
#define SM_X    (SM_OUT + 128 * TILE_OUT * 4)  // uchar X[70*80] = 5600 B
#define SMEM_BYTES (SM_X + 70 * X_PITCH)     // 53472 B

#define MMA_S8(d, a, b0_, b1_)                                                 \
    asm volatile(                                                              \
        "mma.sync.aligned.m16n8k32.row.col.s32.s8.s8.s32 "                     \
        "{%0,%1,%2,%3},{%4,%5,%6,%7},{%8,%9},{%0,%1,%2,%3};"                   \
        : "+r"((d)[0]), "+r"((d)[1]), "+r"((d)[2]), "+r"((d)[3])               \
        : "r"((a)[0]), "r"((a)[1]), "r"((a)[2]), "r"((a)[3]),                  \
          "r"(b0_), "r"(b1_))

__global__ void __launch_bounds__(NTHREADS, 2)
binconv_kernel(const float* __restrict__ I, const float* __restrict__ W,
               const float* __restrict__ TP, const float* __restrict__ TMi,
               const float* __restrict__ PS, const float* __restrict__ MS,
               float* __restrict__ out)
{
    extern __shared__ char smem[];
    int*           CV  = (int*)(smem + SM_CV);
    float*         OUT = (float*)(smem + SM_OUT);
    unsigned char* X   = (unsigned char*)(smem + SM_X);

    const int tid  = threadIdx.x;
    const int lane = tid & 31;
    const int wid  = tid >> 5;       // 0..7 -> m16 tile id (8 * 16 = M 128)
    const int gr   = lane >> 2;      // 0..7
    const int tg   = lane & 3;       // 0..3

    const int co   = tid & 127;
    const int half = tid >> 7;
    const float rtp = TP[co], rtm = TMi[co], rps = PS[co], rms = MS[co];

    // ---- stationary A fragments (weight signs): 56 regs/thread ----
    uint32_t A[KSTEPS][4];
    #pragma unroll
    for (int s = 0; s < KSTEPS; s++) {
        #pragma unroll
        for (int j = 0; j < 4; j++) {
            const int row = wid * 16 + gr + (j & 1) * 8;
            const int kap = 32 * s + (j >> 1) * 16 + tg * 4;
            uint32_t r = 0;
            #pragma unroll
            for (int i = 0; i < 4; i++) {
                const int kk = kap + i;
                const float w = W[row * 448 + (kk & 63) * 7 + (kk >> 6)];
                r |= ((w < 0.f) ? 0xFFu : 0x01u) << (8 * i);
            }
            A[s][j] = r;
        }
    }

    // ---- cross-tile prefetch registers: 5 items x 4 floats ----
    float pf[5][4];

    auto prefetch = [&](unsigned g) {
        if (g >= TOTAL_TILES) return;
        const int b  = (int)(g / TILES_PER_B);
        const int P0 = ((int)g - b * TILES_PER_B) * TILE_OUT * 2;
        const float* Ib = I + (size_t)b * (size_t)CIN * LEN;
        #pragma unroll
        for (int it = 0; it < 5; it++) {
            const int idx = tid + it * NTHREADS;
            if (idx < 16 * 70) {
                const int ci4 = idx / 70;
                const int p   = idx - ci4 * 70;
                const int gl  = P0 - 3 + p;
                const bool inb = (gl >= 0) && (gl < LEN);
                const float* ip = Ib + (size_t)(ci4 * 4) * LEN + gl;
                pf[it][0] = inb ? ip[0]       : -1.f;
                pf[it][1] = inb ? ip[LEN]     : -1.f;
                pf[it][2] = inb ? ip[2 * LEN] : -1.f;
                pf[it][3] = inb ? ip[3 * LEN] : -1.f;
            }
        }
    };

    unsigned g = (unsigned)blockIdx.x;
    prefetch(g);

    while (g < TOTAL_TILES) {
        const unsigned gn = g + GRID;
        const int b  = (int)(g / TILES_PER_B);
        const int jt = (int)g - b * TILES_PER_B;
        const int t0 = jt * TILE_OUT;
        const int nt = min(TILE_OUT, LOUT - t0);

        // ---- convert prefetched floats -> sign tile X[p][ci] ----
        #pragma unroll
        for (int it = 0; it < 5; it++) {
            const int idx = tid + it * NTHREADS;
            if (idx < 16 * 70) {
                const int ci4 = idx / 70;
                const int p   = idx - ci4 * 70;
                const uint32_t pk = ((pf[it][0] < 0.f) ? 0xFFu : 1u)
                                  | (((pf[it][1] < 0.f) ? 0xFFu : 1u) << 8)
                                  | (((pf[it][2] < 0.f) ? 0xFFu : 1u) << 16)
                                  | (((pf[it][3] < 0.f) ? 0xFFu : 1u) << 24);
                *(uint32_t*)&X[p * X_PITCH + ci4 * 4] = pk;
            }
        }
        __syncthreads();            // X ready (also orders prev OUT reads)

        // ---- kick off next tile's global loads (hidden under MMA) ----
        prefetch(gn);

        // ---- MMA mainloop: 112 IMMA + 224 LDS.32 per warp ----
        int acc[8][4];
        #pragma unroll
        for (int n8 = 0; n8 < 8; n8++)
            #pragma unroll
            for (int r = 0; r < 4; r++) acc[n8][r] = 0;

        #pragma unroll
        for (int s = 0; s < KSTEPS; s++) {
            #pragma unroll
            for (int n8 = 0; n8 < 8; n8++) {
                const int prel = n8 * 8 + gr + (s >> 1);
                const uint32_t* bp =
                    (const uint32_t*)&X[prel * X_PITCH + (s & 1) * 32 + tg * 4];
                const uint32_t b0 = bp[0];
                const uint32_t b1 = bp[4];
                MMA_S8(acc[n8], A[s], b0, b1);
            }
        }

        // ---- stage conv results to CV[n][co] (conflict-free STS) ----
        #pragma unroll
        for (int n8 = 0; n8 < 8; n8++) {
            const int n0 = n8 * 8 + tg * 2;
            const int r0 = wid * 16 + gr;
            CV[n0 * CV_PITCH + r0]           = acc[n8][0];
            CV[(n0 + 1) * CV_PITCH + r0]     = acc[n8][1];
            CV[n0 * CV_PITCH + r0 + 8]       = acc[n8][2];
            CV[(n0 + 1) * CV_PITCH + r0 + 8] = acc[n8][3];
        }
        __syncthreads();            // CV ready; all MMA reads of X done

        // ---- pool(7,2) + threshold -> OUT[co][jo] (smem, conflict-free) ----
        {
            const int jo0 = half * 15;
            if (jo0 < nt) {
                int qa = max(CV[(2 * jo0) * CV_PITCH + co],
                             CV[(2 * jo0 + 1) * CV_PITCH + co]);
                int qb = max(CV[(2 * jo0 + 2) * CV_PITCH + co],
                             CV[(2 * jo0 + 3) * CV_PITCH + co]);
                #pragma unroll
                for (int k = 0; k < 15; k++) {
                    const int jo = jo0 + k;
                    if (jo < nt && jo < 29) {
                        const int l0 = CV[(2 * jo + 4) * CV_PITCH + co];
                        const int l1 = CV[(2 * jo + 5) * CV_PITCH + co];
                        const int l2 = CV[(2 * jo + 6) * CV_PITCH + co];
                        const int qc = max(l0, l1);
                        const int mi = max(max(qa, qb), max(qc, l2));
                        const float mx = (float)mi;
                        const float pos = (mx > rtp) ? rps : -rps;
                        const float neg = (mx > rtm) ? rms : -rms;
                        OUT[co * TILE_OUT + jo] = (mx >= 0.f) ? pos : neg;
                        qa = qb; qb = qc;
                    }
                }
            }
        }
        __syncthreads();            // OUT ready

        // ---- coalesced store: warp streams rows, lane = jo ----
        if (lane < nt) {
            #pragma unroll
            for (int it = 0; it < 16; it++) {
                const int row = wid + it * 8;           // co row 0..127
                const float v = OUT[row * TILE_OUT + lane];
                out[((size_t)b * COUT + row) * LOUT + t0 + lane] = v;
            }
        }

        g = gn;
    }
}

extern "C" void kernel_launch(void* const* d_in, const int* in_sizes, int n_in,
                              void* d_out, int out_size) {
    const float* I  = (const float*)d_in[0];
    const float* W  = (const float*)d_in[1];
    const float* tp = (const float*)d_in[2];
    const float* tm = (const float*)d_in[3];
    const float* ps = (const float*)d_in[4];
    const float* ms = (const float*)d_in[5];
    float* out = (float*)d_out;

    cudaFuncSetAttribute(binconv_kernel,
                         cudaFuncAttributeMaxDynamicSharedMemorySize, SMEM_BYTES);
    binconv_kernel<<<GRID, NTHREADS, SMEM_BYTES>>>(I, W, tp, tm, ps, ms, out);
}

// round 7
// speedup vs baseline: 2.2156x; 1.0021x over previous
#include <cuda_runtime.h>
#include <cstdint>

// ============================================================================
// Binary conv1d (sign x sign) + maxpool(7,2) + per-channel threshold.
// IMMA mma.sync.m16n8k32.s8, cross-tile register prefetch, 2 CTAs/SM.
// NEW: co-resident CTA pair (bid, bid+148) is STAGGERED by ~half a round so
// one CTA's MMA phase covers the other's epilogue (breaks phase-lock).
// ============================================================================

#define BATCH 64
#define CIN 64
#define LEN 16384
#define COUT 128
#define LOUT 8189
#define TILE_OUT 29
#define TILES_PER_B 283
#define TOTAL_TILES (BATCH * TILES_PER_B)   // 18112
#define NTHREADS 256
#define GRID 296                             // 2 CTAs per SM

#define KSTEPS 14              // K = 448 = 14 * 32
#define X_PITCH 80             // 64 B + 16 pad: conflict-free LDS.32 frag loads
#define CV_PITCH 129

#define STAGGER_CYC 12000ULL   // ~solo MMA phase; self-corrects downward

// dynamic smem layout (bytes)
#define SM_CV   0                            // int  CV[64*129]  = 33024 B
#define SM_OUT  (64 * CV_PITCH * 4)          // float OUT[128*29] = 14848 B
#define SM_X    (SM_OUT + 128 * TILE_OUT * 4)  // uchar X[70*80] = 5600 B
#define SMEM_BYTES (SM_X + 70 * X_PITCH)     // 53472 B

#define MMA_S8(d, a, b0_, b1_)                                                 \
    asm volatile(                                                              \
        "mma.sync.aligned.m16n8k32.row.col.s32.s8.s8.s32 "                     \
        "{%0,%1,%2,%3},{%4,%5,%6,%7},{%8,%9},{%0,%1,%2,%3};"                   \
        : "+r"((d)[0]), "+r"((d)[1]), "+r"((d)[2]), "+r"((d)[3])               \
        : "r"((a)[0]), "r"((a)[1]), "r"((a)[2]), "r"((a)[3]),                  \
          "r"(b0_), "r"(b1_))

__global__ void __launch_bounds__(NTHREADS, 2)
binconv_kernel(const float* __restrict__ I, const float* __restrict__ W,
               const float* __restrict__ TP, const float* __restrict__ TMi,
               const float* __restrict__ PS, const float* __restrict__ MS,
               float* __restrict__ out)
{
    extern __shared__ char smem[];
    int*           CV  = (int*)(smem + SM_CV);
    float*         OUT = (float*)(smem + SM_OUT);
    unsigned char* X   = (unsigned char*)(smem + SM_X);

    const int tid  = threadIdx.x;
    const int lane = tid & 31;
    const int wid  = tid >> 5;       // 0..7 -> m16 tile id (8 * 16 = M 128)
    const int gr   = lane >> 2;      // 0..7
    const int tg   = lane & 3;       // 0..3

    const int co   = tid & 127;
    const int half = tid >> 7;
    const float rtp = TP[co], rtm = TMi[co], rps = PS[co], rms = MS[co];

    // ---- stationary A fragments (weight signs): 56 regs/thread ----
    uint32_t A[KSTEPS][4];
    #pragma unroll
    for (int s = 0; s < KSTEPS; s++) {
        #pragma unroll
        for (int j = 0; j < 4; j++) {
            const int row = wid * 16 + gr + (j & 1) * 8;
            const int kap = 32 * s + (j >> 1) * 16 + tg * 4;
            uint32_t r = 0;
            #pragma unroll
            for (int i = 0; i < 4; i++) {
                const int kk = kap + i;
                const float w = W[row * 448 + (kk & 63) * 7 + (kk >> 6)];
                r |= ((w < 0.f) ? 0xFFu : 0x01u) << (8 * i);
            }
            A[s][j] = r;
        }
    }

    // ---- stagger the second co-resident CTA (pair = bid, bid+148) ----
    if (blockIdx.x >= 148) {
        const unsigned long long tstart = clock64();
        while (clock64() - tstart < STAGGER_CYC) { }
    }

    // ---- cross-tile prefetch registers: 5 items x 4 floats ----
    float pf[5][4];

    auto prefetch = [&](unsigned g) {
        if (g >= TOTAL_TILES) return;
        const int b  = (int)(g / TILES_PER_B);
        const int P0 = ((int)g - b * TILES_PER_B) * TILE_OUT * 2;
        const float* Ib = I + (size_t)b * (size_t)CIN * LEN;
        #pragma unroll
        for (int it = 0; it < 5; it++) {
            const int idx = tid + it * NTHREADS;
            if (idx < 16 * 70) {
                const int ci4 = idx / 70;
                const int p   = idx - ci4 * 70;
                const int gl  = P0 - 3 + p;
                const bool inb = (gl >= 0) && (gl < LEN);
                const float* ip = Ib + (size_t)(ci4 * 4) * LEN + gl;
                pf[it][0] = inb ? ip[0]       : -1.f;
                pf[it][1] = inb ? ip[LEN]     : -1.f;
                pf[it][2] = inb ? ip[2 * LEN] : -1.f;
                pf[it][3] = inb ? ip[3 * LEN] : -1.f;
            }
        }
    };

    unsigned g = (unsigned)blockIdx.x;
    prefetch(g);

    while (g < TOTAL_TILES) {
        const unsigned gn = g + GRID;
        const int b  = (int)(g / TILES_PER_B);
        const int jt = (int)g - b * TILES_PER_B;
        const int t0 = jt * TILE_OUT;
        const int nt = min(TILE_OUT, LOUT - t0);

        // ---- convert prefetched floats -> sign tile X[p][ci] ----
        #pragma unroll
        for (int it = 0; it < 5; it++) {
            const int idx = tid + it * NTHREADS;
            if (idx < 16 * 70) {
                const int ci4 = idx / 70;
                const int p   = idx - ci4 * 70;
                const uint32_t pk = ((pf[it][0] < 0.f) ? 0xFFu : 1u)
                                  | (((pf[it][1] < 0.f) ? 0xFFu : 1u) << 8)
                                  | (((pf[it][2] < 0.f) ? 0xFFu : 1u) << 16)
                                  | (((pf[it][3] < 0.f) ? 0xFFu : 1u) << 24);
                *(uint32_t*)&X[p * X_PITCH + ci4 * 4] = pk;
            }
        }
        __syncthreads();            // X ready (also orders prev OUT reads)

        // ---- kick off next tile's global loads (hidden under MMA) ----
        prefetch(gn);

        // ---- MMA mainloop: 112 IMMA + 224 LDS.32 per warp ----
        int acc[8][4];
        #pragma unroll
        for (int n8 = 0; n8 < 8; n8++)
            #pragma unroll
            for (int r = 0; r < 4; r++) acc[n8][r] = 0;

        #pragma unroll
        for (int s = 0; s < KSTEPS; s++) {
            #pragma unroll
            for (int n8 = 0; n8 < 8; n8++) {
                const int prel = n8 * 8 + gr + (s >> 1);
                const uint32_t* bp =
                    (const uint32_t*)&X[prel * X_PITCH + (s & 1) * 32 + tg * 4];
                const uint32_t b0 = bp[0];
                const uint32_t b1 = bp[4];
                MMA_S8(acc[n8], A[s], b0, b1);
            }
        }

        // ---- stage conv results to CV[n][co] (conflict-free STS) ----
        #pragma unroll
        for (int n8 = 0; n8 < 8; n8++) {
            const int n0 = n8 * 8 + tg * 2;
            const int r0 = wid * 16 + gr;
            CV[n0 * CV_PITCH + r0]           = acc[n8][0];
            CV[(n0 + 1) * CV_PITCH + r0]     = acc[n8][1];
            CV[n0 * CV_PITCH + r0 + 8]       = acc[n8][2];
            CV[(n0 + 1) * CV_PITCH + r0 + 8] = acc[n8][3];
        }
        __syncthreads();            // CV ready; all MMA reads of X done

        // ---- pool(7,2) + threshold -> OUT[co][jo] (smem, conflict-free) ----
        {
            const int jo0 = half * 15;
            if (jo0 < nt) {
                int qa = max(CV[(2 * jo0) * CV_PITCH + co],
                             CV[(2 * jo0 + 1) * CV_PITCH + co]);
                int qb = max(CV[(2 * jo0 + 2) * CV_PITCH + co],
                             CV[(2 * jo0 + 3) * CV_PITCH + co]);
                #pragma unroll
                for (int k = 0; k < 15; k++) {
                    const int jo = jo0 + k;
                    if (jo < nt && jo < 29) {
                        const int l0 = CV[(2 * jo + 4) * CV_PITCH + co];
                        const int l1 = CV[(2 * jo + 5) * CV_PITCH + co];
                        const int l2 = CV[(2 * jo + 6) * CV_PITCH + co];
                        const int qc = max(l0, l1);
                        const int mi = max(max(qa, qb), max(qc, l2));
                        const float mx = (float)mi;
                        const float pos = (mx > rtp) ? rps : -rps;
                        const float neg = (mx > rtm) ? rms : -rms;
                        OUT[co * TILE_OUT + jo] = (mx >= 0.f) ? pos : neg;
                        qa = qb; qb = qc;
                    }
                }
            }
        }
        __syncthreads();            // OUT ready

        // ---- coalesced store: warp streams rows, lane = jo ----
        if (lane < nt) {
            #pragma unroll
            for (int it = 0; it < 16; it++) {
                const int row = wid + it * 8;           // co row 0..127
                const float v = OUT[row * TILE_OUT + lane];
                out[((size_t)b * COUT + row) * LOUT + t0 + lane] = v;
            }
        }

        g = gn;
    }
}

extern "C" void kernel_launch(void* const* d_in, const int* in_sizes, int n_in,
                              void* d_out, int out_size) {
    const float* I  = (const float*)d_in[0];
    const float* W  = (const float*)d_in[1];
    const float* tp = (const float*)d_in[2];
    const float* tm = (const float*)d_in[3];
    const float* ps = (const float*)d_in[4];
    const float* ms = (const float*)d_in[5];
    float* out = (float*)d_out;

    cudaFuncSetAttribute(binconv_kernel,
                         cudaFuncAttributeMaxDynamicSharedMemorySize, SMEM_BYTES);
    binconv_kernel<<<GRID, NTHREADS, SMEM_BYTES>>>(I, W, tp, tm, ps, ms, out);
}

// round 8
// speedup vs baseline: 2.2421x; 1.0120x over previous
#include <cuda_runtime.h>
#include <cstdint>

// ============================================================================
// Binary conv1d (sign x sign) + maxpool(7,2) + per-channel threshold.
// IMMA mma.sync.m16n8k32.s8, cross-tile register prefetch, 2 CTAs/SM.
// This version: NO CV smem roundtrip -- pooling runs on MMA accumulators via
// width-4 quad shuffles; X double-buffered; 2 syncs/tile (was 3).
// ============================================================================

#define BATCH 64
#define CIN 64
#define LEN 16384
#define COUT 128
#define LOUT 8189
#define TILE_OUT 29
#define TILES_PER_B 283
#define TOTAL_TILES (BATCH * TILES_PER_B)   // 18112
#define NTHREADS 256
#define GRID 296                             // 2 CTAs per SM

#define KSTEPS 14              // K = 448 = 14 * 32
#define X_PITCH 80             // 64 B + 16 pad: conflict-free LDS.32 frag loads
#define OUT_PITCH 36           // 4*gr+tg bank pattern -> conflict-free STS

#define MMA_S8(d, a, b0_, b1_)                                                 \
    asm volatile(                                                              \
        "mma.sync.aligned.m16n8k32.row.col.s32.s8.s8.s32 "                     \
        "{%0,%1,%2,%3},{%4,%5,%6,%7},{%8,%9},{%0,%1,%2,%3};"                   \
        : "+r"((d)[0]), "+r"((d)[1]), "+r"((d)[2]), "+r"((d)[3])               \
        : "r"((a)[0]), "r"((a)[1]), "r"((a)[2]), "r"((a)[3]),                  \
          "r"(b0_), "r"(b1_))

__global__ void __launch_bounds__(NTHREADS, 2)
binconv_kernel(const float* __restrict__ I, const float* __restrict__ W,
               const float* __restrict__ TP, const float* __restrict__ TMi,
               const float* __restrict__ PS, const float* __restrict__ MS,
               float* __restrict__ out)
{
    __shared__ float OUT[COUT * OUT_PITCH];           // 18432 B
    __shared__ unsigned char X[2][70 * X_PITCH];      // 2 x 5600 B

    const int tid  = threadIdx.x;
    const int lane = tid & 31;
    const int wid  = tid >> 5;       // 0..7 -> m16 tile id (8 * 16 = M 128)
    const int gr   = lane >> 2;      // 0..7  (quad id; quad owns 2 rows)
    const int tg   = lane & 3;       // 0..3

    // rows this thread produces accumulators for
    const int r0 = wid * 16 + gr;    // row A
    const int r1 = r0 + 8;           // row B

    // thresholds for both rows
    const float rtpA = TP[r0], rtmA = TMi[r0], rpsA = PS[r0], rmsA = MS[r0];
    const float rtpB = TP[r1], rtmB = TMi[r1], rpsB = PS[r1], rmsB = MS[r1];

    // ---- stationary A fragments (weight signs): 56 regs/thread ----
    uint32_t A[KSTEPS][4];
    #pragma unroll
    for (int s = 0; s < KSTEPS; s++) {
        #pragma unroll
        for (int j = 0; j < 4; j++) {
            const int row = wid * 16 + gr + (j & 1) * 8;
            const int kap = 32 * s + (j >> 1) * 16 + tg * 4;
            uint32_t r = 0;
            #pragma unroll
            for (int i = 0; i < 4; i++) {
                const int kk = kap + i;
                const float w = W[row * 448 + (kk & 63) * 7 + (kk >> 6)];
                r |= ((w < 0.f) ? 0xFFu : 0x01u) << (8 * i);
            }
            A[s][j] = r;
        }
    }

    // ---- cross-tile prefetch registers: 5 items x 4 floats ----
    float pf[5][4];

    auto prefetch = [&](unsigned g) {
        if (g >= TOTAL_TILES) return;
        const int b  = (int)(g / TILES_PER_B);
        const int P0 = ((int)g - b * TILES_PER_B) * TILE_OUT * 2;
        const float* Ib = I + (size_t)b * (size_t)CIN * LEN;
        #pragma unroll
        for (int it = 0; it < 5; it++) {
            const int idx = tid + it * NTHREADS;
            if (idx < 16 * 70) {
                const int ci4 = idx / 70;
                const int p   = idx - ci4 * 70;
                const int gl  = P0 - 3 + p;
                const bool inb = (gl >= 0) && (gl < LEN);
                const float* ip = Ib + (size_t)(ci4 * 4) * LEN + gl;
                pf[it][0] = inb ? ip[0]       : -1.f;
                pf[it][1] = inb ? ip[LEN]     : -1.f;
                pf[it][2] = inb ? ip[2 * LEN] : -1.f;
                pf[it][3] = inb ? ip[3 * LEN] : -1.f;
            }
        }
    };

    auto convert = [&](int buf) {
        #pragma unroll
        for (int it = 0; it < 5; it++) {
            const int idx = tid + it * NTHREADS;
            if (idx < 16 * 70) {
                const int ci4 = idx / 70;
                const int p   = idx - ci4 * 70;
                const uint32_t pk = ((pf[it][0] < 0.f) ? 0xFFu : 1u)
                                  | (((pf[it][1] < 0.f) ? 0xFFu : 1u) << 8)
                                  | (((pf[it][2] < 0.f) ? 0xFFu : 1u) << 16)
                                  | (((pf[it][3] < 0.f) ? 0xFFu : 1u) << 24);
                *(uint32_t*)&X[buf][p * X_PITCH + ci4 * 4] = pk;
            }
        }
    };

    unsigned g = (unsigned)blockIdx.x;
    int buf = 0;
    prefetch(g);
    convert(0);
    __syncthreads();

    while (g < TOTAL_TILES) {
        const unsigned gn = g + GRID;
        const int b  = (int)(g / TILES_PER_B);
        const int jt = (int)g - b * TILES_PER_B;
        const int t0 = jt * TILE_OUT;
        const int nt = min(TILE_OUT, LOUT - t0);

        // ---- kick off next tile's global loads (land during MMA) ----
        prefetch(gn);

        // ---- MMA mainloop: 112 IMMA + 224 LDS.32 per warp ----
        int acc[8][4];
        #pragma unroll
        for (int n8 = 0; n8 < 8; n8++)
            #pragma unroll
            for (int r = 0; r < 4; r++) acc[n8][r] = 0;

        const unsigned char* Xc = X[buf];
        #pragma unroll
        for (int s = 0; s < KSTEPS; s++) {
            #pragma unroll
            for (int n8 = 0; n8 < 8; n8++) {
                const int prel = n8 * 8 + gr + (s >> 1);
                const uint32_t* bp =
                    (const uint32_t*)&Xc[prel * X_PITCH + (s & 1) * 32 + tg * 4];
                const uint32_t b0 = bp[0];
                const uint32_t b1 = bp[4];
                MMA_S8(acc[n8], A[s], b0, b1);
            }
        }

        // ---- pool(7,2) + threshold directly on accumulators ----
        // thread (gr,tg) holds, for rows r0 and r1, cv at n = 4x, 4x+1 for
        // x = n8*4 + tg. q[x] = max(cv[2x], cv[2x+1]) is register-local;
        // pooled[jo] = max(q[jo], q[jo+1], q[jo+2], cv_even[jo+3]).
        #pragma unroll
        for (int row = 0; row < 2; row++) {
            int ev[8], q[8];
            #pragma unroll
            for (int n8 = 0; n8 < 8; n8++) {
                ev[n8] = acc[n8][row * 2];
                q[n8]  = max(acc[n8][row * 2], acc[n8][row * 2 + 1]);
            }
            int sh1[8], sh2[8], she[8];
            #pragma unroll
            for (int n8 = 0; n8 < 8; n8++) {
                sh1[n8] = __shfl_sync(0xFFFFFFFFu, q[n8],  (tg + 1) & 3, 4);
                sh2[n8] = __shfl_sync(0xFFFFFFFFu, q[n8],  (tg + 2) & 3, 4);
                she[n8] = __shfl_sync(0xFFFFFFFFu, ev[n8], (tg + 3) & 3, 4);
            }
            const int   rr  = row ? r1 : r0;
            const float rtp = row ? rtpB : rtpA;
            const float rtm = row ? rtmB : rtmA;
            const float rps = row ? rpsB : rpsA;
            const float rms = row ? rmsB : rmsA;
            #pragma unroll
            for (int n8 = 0; n8 < 8; n8++) {
                const int jo = 4 * n8 + tg;
                if (jo < TILE_OUT) {
                    const int n1 = (n8 < 7) ? n8 + 1 : 7;   // safe when selected
                    const int v1 = (tg < 3) ? sh1[n8] : sh1[n1];
                    const int v2 = (tg < 2) ? sh2[n8] : sh2[n1];
                    const int e  = (tg < 1) ? she[n8] : she[n1];
                    const int mi = max(max(q[n8], v1), max(v2, e));
                    const float mx  = (float)mi;
                    const float pos = (mx > rtp) ? rps : -rps;
                    const float neg = (mx > rtm) ? rms : -rms;
                    OUT[rr * OUT_PITCH + jo] = (mx >= 0.f) ? pos : neg;
                }
            }
        }
        __syncthreads();            // OUT ready; X[buf] MMA reads done

        // ---- coalesced store: warp streams rows, lane = jo ----
        if (lane < nt) {
            #pragma unroll
            for (int it = 0; it < 16; it++) {
                const int row = wid + it * 8;           // co row 0..127
                const float v = OUT[row * OUT_PITCH + lane];
                out[((size_t)b * COUT + row) * LOUT + t0 + lane] = v;
            }
        }

        // ---- convert next tile into the other X buffer ----
        if (gn < TOTAL_TILES) convert(buf ^ 1);
        __syncthreads();            // X[buf^1] ready; OUT reads done

        buf ^= 1;
        g = gn;
    }
}

extern "C" void kernel_launch(void* const* d_in, const int* in_sizes, int n_in,
                              void* d_out, int out_size) {
    const float* I  = (const float*)d_in[0];
    const float* W  = (const float*)d_in[1];
    const float* tp = (const float*)d_in[2];
    const float* tm = (const float*)d_in[3];
    const float* ps = (const float*)d_in[4];
    const float* ms = (const float*)d_in[5];
    float* out = (float*)d_out;

    binconv_kernel<<<GRID, NTHREADS>>>(I, W, tp, tm, ps, ms, out);
}

// round 9
// speedup vs baseline: 2.3144x; 1.0322x over previous
#include <cuda_runtime.h>
#include <cstdint>

// ============================================================================
// Binary conv1d (sign x sign) + maxpool(7,2) + per-channel threshold.
// IMMA mma.sync.m16n8k32.s8, 2 CTAs/SM.
// This version: store(prev) and convert(next) are threaded INTO the MMA
// instruction stream (tail work hides in tensor-pipe shadow); OUT and X are
// double-buffered; exactly ONE __syncthreads() per tile.
// ============================================================================

#define BATCH 64
#define CIN 64
#define LEN 16384
#define COUT 128
#define LOUT 8189
#define TILE_OUT 29
#define TILES_PER_B 283
#define TOTAL_TILES (BATCH * TILES_PER_B)   // 18112
#define NTHREADS 256
#define GRID 296                             // 2 CTAs per SM

#define KSTEPS 14              // K = 448 = 14 * 32
#define X_PITCH 80             // 64 B + 16 pad: conflict-free LDS.32 frag loads
#define OUT_PITCH 36

#define MMA_S8(d, a, b0_, b1_)                                                 \
    asm volatile(                                                              \
        "mma.sync.aligned.m16n8k32.row.col.s32.s8.s8.s32 "                     \
        "{%0,%1,%2,%3},{%4,%5,%6,%7},{%8,%9},{%0,%1,%2,%3};"                   \
        : "+r"((d)[0]), "+r"((d)[1]), "+r"((d)[2]), "+r"((d)[3])               \
        : "r"((a)[0]), "r"((a)[1]), "r"((a)[2]), "r"((a)[3]),                  \
          "r"(b0_), "r"(b1_))

__global__ void __launch_bounds__(NTHREADS, 2)
binconv_kernel(const float* __restrict__ I, const float* __restrict__ W,
               const float* __restrict__ TP, const float* __restrict__ TMi,
               const float* __restrict__ PS, const float* __restrict__ MS,
               float* __restrict__ out)
{
    __shared__ float OUT[2][COUT * OUT_PITCH];        // 2 x 18432 B
    __shared__ unsigned char X[2][70 * X_PITCH];      // 2 x 5600 B  (48064 tot)

    const int tid  = threadIdx.x;
    const int lane = tid & 31;
    const int wid  = tid >> 5;       // 0..7 -> m16 tile id (8 * 16 = M 128)
    const int gr   = lane >> 2;      // 0..7  (quad id; quad owns 2 rows)
    const int tg   = lane & 3;       // 0..3

    const int r0 = wid * 16 + gr;    // row A
    const int r1 = r0 + 8;           // row B

    const float rtpA = TP[r0], rtmA = TMi[r0], rpsA = PS[r0], rmsA = MS[r0];
    const float rtpB = TP[r1], rtmB = TMi[r1], rpsB = PS[r1], rmsB = MS[r1];

    // ---- stationary A fragments (weight signs): 56 regs/thread ----
    uint32_t A[KSTEPS][4];
    #pragma unroll
    for (int s = 0; s < KSTEPS; s++) {
        #pragma unroll
        for (int j = 0; j < 4; j++) {
            const int row = wid * 16 + gr + (j & 1) * 8;
            const int kap = 32 * s + (j >> 1) * 16 + tg * 4;
            uint32_t r = 0;
            #pragma unroll
            for (int i = 0; i < 4; i++) {
                const int kk = kap + i;
                const float w = W[row * 448 + (kk & 63) * 7 + (kk >> 6)];
                r |= ((w < 0.f) ? 0xFFu : 0x01u) << (8 * i);
            }
            A[s][j] = r;
        }
    }

    // ---- cross-tile prefetch registers: 5 items x 4 floats ----
    float pf[5][4];

    auto prefetch = [&](unsigned g) {
        if (g >= TOTAL_TILES) return;
        const int b  = (int)(g / TILES_PER_B);
        const int P0 = ((int)g - b * TILES_PER_B) * TILE_OUT * 2;
        const float* Ib = I + (size_t)b * (size_t)CIN * LEN;
        #pragma unroll
        for (int it = 0; it < 5; it++) {
            const int idx = tid + it * NTHREADS;
            if (idx < 16 * 70) {
                const int ci4 = idx / 70;
                const int p   = idx - ci4 * 70;
                const int gl  = P0 - 3 + p;
                const bool inb = (gl >= 0) && (gl < LEN);
                const float* ip = Ib + (size_t)(ci4 * 4) * LEN + gl;
                pf[it][0] = inb ? ip[0]       : -1.f;
                pf[it][1] = inb ? ip[LEN]     : -1.f;
                pf[it][2] = inb ? ip[2 * LEN] : -1.f;
                pf[it][3] = inb ? ip[3 * LEN] : -1.f;
            }
        }
    };

    auto convert = [&](int xb) {
        #pragma unroll
        for (int it = 0; it < 5; it++) {
            const int idx = tid + it * NTHREADS;
            if (idx < 16 * 70) {
                const int ci4 = idx / 70;
                const int p   = idx - ci4 * 70;
                const uint32_t pk = ((pf[it][0] < 0.f) ? 0xFFu : 1u)
                                  | (((pf[it][1] < 0.f) ? 0xFFu : 1u) << 8)
                                  | (((pf[it][2] < 0.f) ? 0xFFu : 1u) << 16)
                                  | (((pf[it][3] < 0.f) ? 0xFFu : 1u) << 24);
                *(uint32_t*)&X[xb][p * X_PITCH + ci4 * 4] = pk;
            }
        }
    };

    unsigned g = (unsigned)blockIdx.x;
    int xb = 0, ob = 0;
    int prev_valid = 0, b_prev = 0, t0_prev = 0, nt_prev = 0;

    prefetch(g);
    convert(0);
    __syncthreads();

    while (g < TOTAL_TILES) {
        const unsigned gn = g + GRID;
        const int b  = (int)(g / TILES_PER_B);
        const int jt = (int)g - b * TILES_PER_B;
        const int t0 = jt * TILE_OUT;
        const int nt = min(TILE_OUT, LOUT - t0);

        // issue next tile's LDGs now; they land during this MMA phase
        prefetch(gn);

        int acc[8][4];
        #pragma unroll
        for (int n8 = 0; n8 < 8; n8++)
            #pragma unroll
            for (int r = 0; r < 4; r++) acc[n8][r] = 0;

        const unsigned char* Xc = X[xb];

        // ---- MMA chunk s = 0..6 ----
        #pragma unroll
        for (int s = 0; s < 7; s++) {
            #pragma unroll
            for (int n8 = 0; n8 < 8; n8++) {
                const int prel = n8 * 8 + gr + (s >> 1);
                const uint32_t* bp =
                    (const uint32_t*)&Xc[prel * X_PITCH + (s & 1) * 32 + tg * 4];
                MMA_S8(acc[n8], A[s], bp[0], bp[4]);
            }
        }

        // ---- store previous tile's output (hidden in tensor shadow) ----
        if (prev_valid && lane < nt_prev) {
            const float* ob_prev = OUT[ob ^ 1];
            #pragma unroll
            for (int it = 0; it < 16; it++) {
                const int row = wid + it * 8;
                out[((size_t)b_prev * COUT + row) * LOUT + t0_prev + lane] =
                    ob_prev[row * OUT_PITCH + lane];
            }
        }

        // ---- MMA chunk s = 7..10 ----
        #pragma unroll
        for (int s = 7; s < 11; s++) {
            #pragma unroll
            for (int n8 = 0; n8 < 8; n8++) {
                const int prel = n8 * 8 + gr + (s >> 1);
                const uint32_t* bp =
                    (const uint32_t*)&Xc[prel * X_PITCH + (s & 1) * 32 + tg * 4];
                MMA_S8(acc[n8], A[s], bp[0], bp[4]);
            }
        }

        // ---- convert next tile into other X buffer (tensor shadow) ----
        if (gn < TOTAL_TILES) convert(xb ^ 1);

        // ---- MMA chunk s = 11..13 ----
        #pragma unroll
        for (int s = 11; s < 14; s++) {
            #pragma unroll
            for (int n8 = 0; n8 < 8; n8++) {
                const int prel = n8 * 8 + gr + (s >> 1);
                const uint32_t* bp =
                    (const uint32_t*)&Xc[prel * X_PITCH + (s & 1) * 32 + tg * 4];
                MMA_S8(acc[n8], A[s], bp[0], bp[4]);
            }
        }

        // ---- pool(7,2) + threshold on accumulators -> OUT[ob] ----
        #pragma unroll
        for (int row = 0; row < 2; row++) {
            int ev[8], q[8];
            #pragma unroll
            for (int n8 = 0; n8 < 8; n8++) {
                ev[n8] = acc[n8][row * 2];
                q[n8]  = max(acc[n8][row * 2], acc[n8][row * 2 + 1]);
            }
            int sh1[8], sh2[8], she[8];
            #pragma unroll
            for (int n8 = 0; n8 < 8; n8++) {
                sh1[n8] = __shfl_sync(0xFFFFFFFFu, q[n8],  (tg + 1) & 3, 4);
                sh2[n8] = __shfl_sync(0xFFFFFFFFu, q[n8],  (tg + 2) & 3, 4);
                she[n8] = __shfl_sync(0xFFFFFFFFu, ev[n8], (tg + 3) & 3, 4);
            }
            const int   rr  = row ? r1 : r0;
            const float rtp = row ? rtpB : rtpA;
            const float rtm = row ? rtmB : rtmA;
            const float rps = row ? rpsB : rpsA;
            const float rms = row ? rmsB : rmsA;
            float* outp = OUT[ob];
            #pragma unroll
            for (int n8 = 0; n8 < 8; n8++) {
                const int jo = 4 * n8 + tg;
                if (jo < TILE_OUT) {
                    const int n1 = (n8 < 7) ? n8 + 1 : 7;
                    const int v1 = (tg < 3) ? sh1[n8] : sh1[n1];
                    const int v2 = (tg < 2) ? sh2[n8] : sh2[n1];
                    const int e  = (tg < 1) ? she[n8] : she[n1];
                    const int mi = max(max(q[n8], v1), max(v2, e));
                    const float mx  = (float)mi;
                    const float pos = (mx > rtp) ? rps : -rps;
                    const float neg = (mx > rtm) ? rms : -rms;
                    outp[rr * OUT_PITCH + jo] = (mx >= 0.f) ? pos : neg;
                }
            }
        }

        __syncthreads();   // OUT[ob] + X[xb^1] visible; X[xb]/OUT[ob^1] free

        prev_valid = 1; b_prev = b; t0_prev = t0; nt_prev = nt;
        ob ^= 1; xb ^= 1;
        g = gn;
    }

    // ---- drain: store the last tile ----
    if (prev_valid && lane < nt_prev) {
        const float* ob_prev = OUT[ob ^ 1];
        #pragma unroll
        for (int it = 0; it < 16; it++) {
            const int row = wid + it * 8;
            out[((size_t)b_prev * COUT + row) * LOUT + t0_prev + lane] =
                ob_prev[row * OUT_PITCH + lane];
        }
    }
}

extern "C" void kernel_launch(void* const* d_in, const int* in_sizes, int n_in,
                              void* d_out, int out_size) {
    const float* I  = (const float*)d_in[0];
    const float* W  = (const float*)d_in[1];
    const float* tp = (const float*)d_in[2];
    const float* tm = (const float*)d_in[3];
    const float* ps = (const float*)d_in[4];
    const float* ms = (const float*)d_in[5];
    float* out = (float*)d_out;

    binconv_kernel<<<GRID, NTHREADS>>>(I, W, tp, tm, ps, ms, out);
}

// round 10
// speedup vs baseline: 4.4076x; 1.9044x over previous
#include <cuda_runtime.h>
#include <cstdint>

// ============================================================================
// Binary conv1d (sign x sign) + maxpool(7,2) + per-channel threshold.
// EXPERIMENT: FP8 e4m3 mma.sync (m16n8k32.f32.e4m3.e4m3.f32) instead of s8 --
// probing whether Blackwell's legacy-mma path runs FP8 faster than INT8.
// Pipeline identical to R9: 2 CTAs/SM, cross-tile register prefetch,
// store/convert threaded into the MMA stream, one __syncthreads per tile.
// Exact math: ±1 as e4m3 (0x38/0xB8), f32 accumulation, |sum| <= 448.
// ============================================================================

#define BATCH 64
#define CIN 64
#define LEN 16384
#define COUT 128
#define LOUT 8189
#define TILE_OUT 29
#define TILES_PER_B 283
#define TOTAL_TILES (BATCH * TILES_PER_B)   // 18112
#define NTHREADS 256
#define GRID 296                             // 2 CTAs per SM

#define KSTEPS 14              // K = 448 = 14 * 32
#define X_PITCH 80             // 64 B + 16 pad: conflict-free LDS.32 frag loads
#define OUT_PITCH 36

#define FP8_P1 0x38u           // e4m3 +1.0
#define FP8_M1 0xB8u           // e4m3 -1.0

#define MMA_F8(d, a, b0_, b1_)                                                 \
    asm volatile(                                                              \
        "mma.sync.aligned.m16n8k32.row.col.f32.e4m3.e4m3.f32 "                 \
        "{%0,%1,%2,%3},{%4,%5,%6,%7},{%8,%9},{%0,%1,%2,%3};"                   \
        : "+f"((d)[0]), "+f"((d)[1]), "+f"((d)[2]), "+f"((d)[3])               \
        : "r"((a)[0]), "r"((a)[1]), "r"((a)[2]), "r"((a)[3]),                  \
          "r"(b0_), "r"(b1_))

__global__ void __launch_bounds__(NTHREADS, 2)
binconv_kernel(const float* __restrict__ I, const float* __restrict__ W,
               const float* __restrict__ TP, const float* __restrict__ TMi,
               const float* __restrict__ PS, const float* __restrict__ MS,
               float* __restrict__ out)
{
    __shared__ float OUT[2][COUT * OUT_PITCH];        // 2 x 18432 B
    __shared__ unsigned char X[2][70 * X_PITCH];      // 2 x 5600 B

    const int tid  = threadIdx.x;
    const int lane = tid & 31;
    const int wid  = tid >> 5;       // 0..7 -> m16 tile id (8 * 16 = M 128)
    const int gr   = lane >> 2;      // 0..7  (quad id; quad owns 2 rows)
    const int tg   = lane & 3;       // 0..3

    const int r0 = wid * 16 + gr;    // row A
    const int r1 = r0 + 8;           // row B

    const float rtpA = TP[r0], rtmA = TMi[r0], rpsA = PS[r0], rmsA = MS[r0];
    const float rtpB = TP[r1], rtmB = TMi[r1], rpsB = PS[r1], rmsB = MS[r1];

    // ---- stationary A fragments (weight signs as e4m3): 56 regs/thread ----
    uint32_t A[KSTEPS][4];
    #pragma unroll
    for (int s = 0; s < KSTEPS; s++) {
        #pragma unroll
        for (int j = 0; j < 4; j++) {
            const int row = wid * 16 + gr + (j & 1) * 8;
            const int kap = 32 * s + (j >> 1) * 16 + tg * 4;
            uint32_t r = 0;
            #pragma unroll
            for (int i = 0; i < 4; i++) {
                const int kk = kap + i;
                const float w = W[row * 448 + (kk & 63) * 7 + (kk >> 6)];
                r |= ((w < 0.f) ? FP8_M1 : FP8_P1) << (8 * i);
            }
            A[s][j] = r;
        }
    }

    // ---- cross-tile prefetch registers: 5 items x 4 floats ----
    float pf[5][4];

    auto prefetch = [&](unsigned g) {
        if (g >= TOTAL_TILES) return;
        const int b  = (int)(g / TILES_PER_B);
        const int P0 = ((int)g - b * TILES_PER_B) * TILE_OUT * 2;
        const float* Ib = I + (size_t)b * (size_t)CIN * LEN;
        #pragma unroll
        for (int it = 0; it < 5; it++) {
            const int idx = tid + it * NTHREADS;
            if (idx < 16 * 70) {
                const int ci4 = idx / 70;
                const int p   = idx - ci4 * 70;
                const int gl  = P0 - 3 + p;
                const bool inb = (gl >= 0) && (gl < LEN);
                const float* ip = Ib + (size_t)(ci4 * 4) * LEN + gl;
                pf[it][0] = inb ? ip[0]       : -1.f;
                pf[it][1] = inb ? ip[LEN]     : -1.f;
                pf[it][2] = inb ? ip[2 * LEN] : -1.f;
                pf[it][3] = inb ? ip[3 * LEN] : -1.f;
            }
        }
    };

    auto convert = [&](int xb) {
        #pragma unroll
        for (int it = 0; it < 5; it++) {
            const int idx = tid + it * NTHREADS;
            if (idx < 16 * 70) {
                const int ci4 = idx / 70;
                const int p   = idx - ci4 * 70;
                const uint32_t pk = ((pf[it][0] < 0.f) ? FP8_M1 : FP8_P1)
                                  | (((pf[it][1] < 0.f) ? FP8_M1 : FP8_P1) << 8)
                                  | (((pf[it][2] < 0.f) ? FP8_M1 : FP8_P1) << 16)
                                  | (((pf[it][3] < 0.f) ? FP8_M1 : FP8_P1) << 24);
                *(uint32_t*)&X[xb][p * X_PITCH + ci4 * 4] = pk;
            }
        }
    };

    unsigned g = (unsigned)blockIdx.x;
    int xb = 0, ob = 0;
    int prev_valid = 0, b_prev = 0, t0_prev = 0, nt_prev = 0;

    prefetch(g);
    convert(0);
    __syncthreads();

    while (g < TOTAL_TILES) {
        const unsigned gn = g + GRID;
        const int b  = (int)(g / TILES_PER_B);
        const int jt = (int)g - b * TILES_PER_B;
        const int t0 = jt * TILE_OUT;
        const int nt = min(TILE_OUT, LOUT - t0);

        // issue next tile's LDGs now; they land during this MMA phase
        prefetch(gn);

        float acc[8][4];
        #pragma unroll
        for (int n8 = 0; n8 < 8; n8++)
            #pragma unroll
            for (int r = 0; r < 4; r++) acc[n8][r] = 0.f;

        const unsigned char* Xc = X[xb];

        // ---- MMA chunk s = 0..6 ----
        #pragma unroll
        for (int s = 0; s < 7; s++) {
            #pragma unroll
            for (int n8 = 0; n8 < 8; n8++) {
                const int prel = n8 * 8 + gr + (s >> 1);
                const uint32_t* bp =
                    (const uint32_t*)&Xc[prel * X_PITCH + (s & 1) * 32 + tg * 4];
                MMA_F8(acc[n8], A[s], bp[0], bp[4]);
            }
        }

        // ---- store previous tile's output (hidden in tensor shadow) ----
        if (prev_valid && lane < nt_prev) {
            const float* ob_prev = OUT[ob ^ 1];
            #pragma unroll
            for (int it = 0; it < 16; it++) {
                const int row = wid + it * 8;
                out[((size_t)b_prev * COUT + row) * LOUT + t0_prev + lane] =
                    ob_prev[row * OUT_PITCH + lane];
            }
        }

        // ---- MMA chunk s = 7..10 ----
        #pragma unroll
        for (int s = 7; s < 11; s++) {
            #pragma unroll
            for (int n8 = 0; n8 < 8; n8++) {
                const int prel = n8 * 8 + gr + (s >> 1);
                const uint32_t* bp =
                    (const uint32_t*)&Xc[prel * X_PITCH + (s & 1) * 32 + tg * 4];
                MMA_F8(acc[n8], A[s], bp[0], bp[4]);
            }
        }

        // ---- convert next tile into other X buffer (tensor shadow) ----
        if (gn < TOTAL_TILES) convert(xb ^ 1);

        // ---- MMA chunk s = 11..13 ----
        #pragma unroll
        for (int s = 11; s < 14; s++) {
            #pragma unroll
            for (int n8 = 0; n8 < 8; n8++) {
                const int prel = n8 * 8 + gr + (s >> 1);
                const uint32_t* bp =
                    (const uint32_t*)&Xc[prel * X_PITCH + (s & 1) * 32 + tg * 4];
                MMA_F8(acc[n8], A[s], bp[0], bp[4]);
            }
        }

        // ---- pool(7,2) + threshold on accumulators -> OUT[ob] ----
        #pragma unroll
        for (int row = 0; row < 2; row++) {
            float ev[8], q[8];
            #pragma unroll
            for (int n8 = 0; n8 < 8; n8++) {
                ev[n8] = acc[n8][row * 2];
                q[n8]  = fmaxf(acc[n8][row * 2], acc[n8][row * 2 + 1]);
            }
            float sh1[8], sh2[8], she[8];
            #pragma unroll
            for (int n8 = 0; n8 < 8; n8++) {
                sh1[n8] = __shfl_sync(0xFFFFFFFFu, q[n8],  (tg + 1) & 3, 4);
                sh2[n8] = __shfl_sync(0xFFFFFFFFu, q[n8],  (tg + 2) & 3, 4);
                she[n8] = __shfl_sync(0xFFFFFFFFu, ev[n8], (tg + 3) & 3, 4);
            }
            const int   rr  = row ? r1 : r0;
            const float rtp = row ? rtpB : rtpA;
            const float rtm = row ? rtmB : rtmA;
            const float rps = row ? rpsB : rpsA;
            const float rms = row ? rmsB : rmsA;
            float* outp = OUT[ob];
            #pragma unroll
            for (int n8 = 0; n8 < 8; n8++) {
                const int jo = 4 * n8 + tg;
                if (jo < TILE_OUT) {
                    const int n1 = (n8 < 7) ? n8 + 1 : 7;
                    const float v1 = (tg < 3) ? sh1[n8] : sh1[n1];
                    const float v2 = (tg < 2) ? sh2[n8] : sh2[n1];
                    const float e  = (tg < 1) ? she[n8] : she[n1];
                    const float mx = fmaxf(fmaxf(q[n8], v1), fmaxf(v2, e));
                    const float pos = (mx > rtp) ? rps : -rps;
                    const float neg = (mx > rtm) ? rms : -rms;
                    outp[rr * OUT_PITCH + jo] = (mx >= 0.f) ? pos : neg;
                }
            }
        }

        __syncthreads();   // OUT[ob] + X[xb^1] visible; X[xb]/OUT[ob^1] free

        prev_valid = 1; b_prev = b; t0_prev = t0; nt_prev = nt;
        ob ^= 1; xb ^= 1;
        g = gn;
    }

    // ---- drain: store the last tile ----
    if (prev_valid && lane < nt_prev) {
        const float* ob_prev = OUT[ob ^ 1];
        #pragma unroll
        for (int it = 0; it < 16; it++) {
            const int row = wid + it * 8;
            out[((size_t)b_prev * COUT + row) * LOUT + t0_prev + lane] =
                ob_prev[row * OUT_PITCH + lane];
        }
    }
}

extern "C" void kernel_launch(void* const* d_in, const int* in_sizes, int n_in,
                              void* d_out, int out_size) {
    const float* I  = (const float*)d_in[0];
    const float* W  = (const float*)d_in[1];
    const float* tp = (const float*)d_in[2];
    const float* tm = (const float*)d_in[3];
    const float* ps = (const float*)d_in[4];
    const float* ms = (const float*)d_in[5];
    float* out = (float*)d_out;

    binconv_kernel<<<GRID, NTHREADS>>>(I, W, tp, tm, ps, ms, out);
}

// round 11
// speedup vs baseline: 4.4781x; 1.0160x over previous
#include <cuda_runtime.h>
#include <cstdint>

// ============================================================================
// Binary conv1d (sign x sign) + maxpool(7,2) + per-channel threshold.
// FP8 e4m3 mma.sync.m16n8k32 (legacy path runs FP8 ~4x faster than s8 on
// sm_103). This round: LDS.64 B-fragments via permuted X layout (pitch 96)
// and PRMT-based sign conversion -- cutting non-MMA issue slots ~25%.
// ============================================================================

#define BATCH 64
#define CIN 64
#define LEN 16384
#define COUT 128
#define LOUT 8189
#define TILE_OUT 29
#define TILES_PER_B 283
#define TOTAL_TILES (BATCH * TILES_PER_B)   // 18112
#define NTHREADS 256
#define GRID 296                             // 2 CTAs per SM

#define KSTEPS 14              // K = 448 = 14 * 32
#define X_PITCH 96             // permuted row: LDS.64 conflict-free
#define OUT_PITCH 36

// dynamic smem layout
#define SM_OUT  0                                   // float OUT[2][128*36]
#define SM_X    (2 * COUT * OUT_PITCH * 4)          // uchar X[2][70*96]
#define SMEM_BYTES (SM_X + 2 * 70 * X_PITCH)        // 50304 B

#define FP8_P1 0x38u           // e4m3 +1.0

#define MMA_F8(d, a, b0_, b1_)                                                 \
    asm volatile(                                                              \
        "mma.sync.aligned.m16n8k32.row.col.f32.e4m3.e4m3.f32 "                 \
        "{%0,%1,%2,%3},{%4,%5,%6,%7},{%8,%9},{%0,%1,%2,%3};"                   \
        : "+f"((d)[0]), "+f"((d)[1]), "+f"((d)[2]), "+f"((d)[3])               \
        : "r"((a)[0]), "r"((a)[1]), "r"((a)[2]), "r"((a)[3]),                  \
          "r"(b0_), "r"(b1_))

__global__ void __launch_bounds__(NTHREADS, 2)
binconv_kernel(const float* __restrict__ I, const float* __restrict__ W,
               const float* __restrict__ TP, const float* __restrict__ TMi,
               const float* __restrict__ PS, const float* __restrict__ MS,
               float* __restrict__ out)
{
    extern __shared__ char smem[];
    float*         OUT = (float*)(smem + SM_OUT);     // [2][COUT*OUT_PITCH]
    unsigned char* X   = (unsigned char*)(smem + SM_X);  // [2][70*X_PITCH]

    const int tid  = threadIdx.x;
    const int lane = tid & 31;
    const int wid  = tid >> 5;       // 0..7 -> m16 tile id (8 * 16 = M 128)
    const int gr   = lane >> 2;      // 0..7  (quad id; quad owns 2 rows)
    const int tg   = lane & 3;       // 0..3

    const int r0 = wid * 16 + gr;    // row A
    const int r1 = r0 + 8;           // row B

    const float rtpA = TP[r0], rtmA = TMi[r0], rpsA = PS[r0], rmsA = MS[r0];
    const float rtpB = TP[r1], rtmB = TMi[r1], rpsB = PS[r1], rmsB = MS[r1];

    // ---- stationary A fragments (weight signs as e4m3): 56 regs/thread ----
    uint32_t A[KSTEPS][4];
    #pragma unroll
    for (int s = 0; s < KSTEPS; s++) {
        #pragma unroll
        for (int j = 0; j < 4; j++) {
            const int row = wid * 16 + gr + (j & 1) * 8;
            const int kap = 32 * s + (j >> 1) * 16 + tg * 4;
            uint32_t r = 0;
            #pragma unroll
            for (int i = 0; i < 4; i++) {
                const int kk = kap + i;
                const float w = W[row * 448 + (kk & 63) * 7 + (kk >> 6)];
                r |= (FP8_P1 | ((w < 0.f) ? 0x80u : 0u)) << (8 * i);
            }
            A[s][j] = r;
        }
    }

    // ---- cross-tile prefetch registers: 5 items x 4 floats ----
    float pf[5][4];

    auto prefetch = [&](unsigned g) {
        if (g >= TOTAL_TILES) return;
        const int b  = (int)(g / TILES_PER_B);
        const int P0 = ((int)g - b * TILES_PER_B) * TILE_OUT * 2;
        const float* Ib = I + (size_t)b * (size_t)CIN * LEN;
        #pragma unroll
        for (int it = 0; it < 5; it++) {
            const int idx = tid + it * NTHREADS;
            if (idx < 16 * 70) {
                const int ci4 = idx / 70;
                const int p   = idx - ci4 * 70;
                const int gl  = P0 - 3 + p;
                const bool inb = (gl >= 0) && (gl < LEN);
                const float* ip = Ib + (size_t)(ci4 * 4) * LEN + gl;
                pf[it][0] = inb ? ip[0]       : -1.f;
                pf[it][1] = inb ? ip[LEN]     : -1.f;
                pf[it][2] = inb ? ip[2 * LEN] : -1.f;
                pf[it][3] = inb ? ip[3 * LEN] : -1.f;
            }
        }
    };

    // convert: sign-gather via PRMT; word permutation [0,4,1,5,2,6,3,7]
    // within each 32B half-row so (b0,b1) become one LDS.64.
    auto convert = [&](int xb) {
        unsigned char* Xb = X + xb * (70 * X_PITCH);
        #pragma unroll
        for (int it = 0; it < 5; it++) {
            const int idx = tid + it * NTHREADS;
            if (idx < 16 * 70) {
                const int ci4 = idx / 70;
                const int p   = idx - ci4 * 70;
                const uint32_t u0 = __float_as_uint(pf[it][0]);
                const uint32_t u1 = __float_as_uint(pf[it][1]);
                const uint32_t u2 = __float_as_uint(pf[it][2]);
                const uint32_t u3 = __float_as_uint(pf[it][3]);
                const uint32_t t  = __byte_perm(u0, u1, 0x0073);
                const uint32_t s2 = __byte_perm(u2, u3, 0x7300);
                const uint32_t r  = __byte_perm(t, s2, 0x7610);
                const uint32_t pk = (r & 0x80808080u) | 0x38383838u;
                const int h  = ci4 >> 3;
                const int w  = ci4 & 7;
                const int wp = ((w & 3) << 1) + (w >> 2);
                *(uint32_t*)&Xb[p * X_PITCH + h * 32 + wp * 4] = pk;
            }
        }
    };

    unsigned g = (unsigned)blockIdx.x;
    int xb = 0, ob = 0;
    int prev_valid = 0, b_prev = 0, t0_prev = 0, nt_prev = 0;

    prefetch(g);
    convert(0);
    __syncthreads();

    while (g < TOTAL_TILES) {
        const unsigned gn = g + GRID;
        const int b  = (int)(g / TILES_PER_B);
        const int jt = (int)g - b * TILES_PER_B;
        const int t0 = jt * TILE_OUT;
        const int nt = min(TILE_OUT, LOUT - t0);

        // issue next tile's LDGs now; they land during this MMA phase
        prefetch(gn);

        float acc[8][4];
        #pragma unroll
        for (int n8 = 0; n8 < 8; n8++)
            #pragma unroll
            for (int r = 0; r < 4; r++) acc[n8][r] = 0.f;

        const unsigned char* Xc = X + xb * (70 * X_PITCH);

        // ---- MMA chunk s = 0..6 (LDS.64 B fragments) ----
        #pragma unroll
        for (int s = 0; s < 7; s++) {
            #pragma unroll
            for (int n8 = 0; n8 < 8; n8++) {
                const int prel = n8 * 8 + gr + (s >> 1);
                const uint2 bv = *(const uint2*)
                    &Xc[prel * X_PITCH + (s & 1) * 32 + tg * 8];
                MMA_F8(acc[n8], A[s], bv.x, bv.y);
            }
        }

        // ---- store previous tile's output (hidden in tensor shadow) ----
        if (prev_valid && lane < nt_prev) {
            const float* op = OUT + (ob ^ 1) * (COUT * OUT_PITCH);
            #pragma unroll
            for (int it = 0; it < 16; it++) {
                const int row = wid + it * 8;
                out[((size_t)b_prev * COUT + row) * LOUT + t0_prev + lane] =
                    op[row * OUT_PITCH + lane];
            }
        }

        // ---- MMA chunk s = 7..10 ----
        #pragma unroll
        for (int s = 7; s < 11; s++) {
            #pragma unroll
            for (int n8 = 0; n8 < 8; n8++) {
                const int prel = n8 * 8 + gr + (s >> 1);
                const uint2 bv = *(const uint2*)
                    &Xc[prel * X_PITCH + (s & 1) * 32 + tg * 8];
                MMA_F8(acc[n8], A[s], bv.x, bv.y);
            }
        }

        // ---- convert next tile into other X buffer (tensor shadow) ----
        if (gn < TOTAL_TILES) convert(xb ^ 1);

        // ---- MMA chunk s = 11..13 ----
        #pragma unroll
        for (int s = 11; s < 14; s++) {
            #pragma unroll
            for (int n8 = 0; n8 < 8; n8++) {
                const int prel = n8 * 8 + gr + (s >> 1);
                const uint2 bv = *(const uint2*)
                    &Xc[prel * X_PITCH + (s & 1) * 32 + tg * 8];
                MMA_F8(acc[n8], A[s], bv.x, bv.y);
            }
        }

        // ---- pool(7,2) + threshold on accumulators -> OUT[ob] ----
        #pragma unroll
        for (int row = 0; row < 2; row++) {
            float ev[8], q[8];
            #pragma unroll
            for (int n8 = 0; n8 < 8; n8++) {
                ev[n8] = acc[n8][row * 2];
                q[n8]  = fmaxf(acc[n8][row * 2], acc[n8][row * 2 + 1]);
            }
            float sh1[8], sh2[8], she[8];
            #pragma unroll
            for (int n8 = 0; n8 < 8; n8++) {
                sh1[n8] = __shfl_sync(0xFFFFFFFFu, q[n8],  (tg + 1) & 3, 4);
                sh2[n8] = __shfl_sync(0xFFFFFFFFu, q[n8],  (tg + 2) & 3, 4);
                she[n8] = __shfl_sync(0xFFFFFFFFu, ev[n8], (tg + 3) & 3, 4);
            }
            const int   rr  = row ? r1 : r0;
            const float rtp = row ? rtpB : rtpA;
            const float rtm = row ? rtmB : rtmA;
            const float rps = row ? rpsB : rpsA;
            const float rms = row ? rmsB : rmsA;
            float* outp = OUT + ob * (COUT * OUT_PITCH);
            #pragma unroll
            for (int n8 = 0; n8 < 8; n8++) {
                const int jo = 4 * n8 + tg;
                if (jo < TILE_OUT) {
                    const int n1 = (n8 < 7) ? n8 + 1 : 7;
                    const float v1 = (tg < 3) ? sh1[n8] : sh1[n1];
                    const float v2 = (tg < 2) ? sh2[n8] : sh2[n1];
                    const float e  = (tg < 1) ? she[n8] : she[n1];
                    const float mx = fmaxf(fmaxf(q[n8], v1), fmaxf(v2, e));
                    const float pos = (mx > rtp) ? rps : -rps;
                    const float neg = (mx > rtm) ? rms : -rms;
                    outp[rr * OUT_PITCH + jo] = (mx >= 0.f) ? pos : neg;
                }
            }
        }

        __syncthreads();   // OUT[ob] + X[xb^1] visible; X[xb]/OUT[ob^1] free

        prev_valid = 1; b_prev = b; t0_prev = t0; nt_prev = nt;
        ob ^= 1; xb ^= 1;
        g = gn;
    }

    // ---- drain: store the last tile ----
    if (prev_valid && lane < nt_prev) {
        const float* op = OUT + (ob ^ 1) * (COUT * OUT_PITCH);
        #pragma unroll
        for (int it = 0; it < 16; it++) {
            const int row = wid + it * 8;
            out[((size_t)b_prev * COUT + row) * LOUT + t0_prev + lane] =
                op[row * OUT_PITCH + lane];
        }
    }
}

extern "C" void kernel_launch(void* const* d_in, const int* in_sizes, int n_in,
                              void* d_out, int out_size) {
    const float* I  = (const float*)d_in[0];
    const float* W  = (const float*)d_in[1];
    const float* tp = (const float*)d_in[2];
    const float* tm = (const float*)d_in[3];
    const float* ps = (const float*)d_in[4];
    const float* ms = (const float*)d_in[5];
    float* out = (float*)d_out;

    cudaFuncSetAttribute(binconv_kernel,
                         cudaFuncAttributeMaxDynamicSharedMemorySize, SMEM_BYTES);
    binconv_kernel<<<GRID, NTHREADS, SMEM_BYTES>>>(I, W, tp, tm, ps, ms, out);
}